// round 16
// baseline (speedup 1.0000x reference)
#include <cuda_runtime.h>
#include <cuda_bf16.h>
#include <cuda_fp16.h>
#include <math.h>
#include <stdint.h>

// ---------------------------------------------------------------------------
// MoE FFN top-2/8, H=1024, I=4096, T<=8192, fp32 in/out.
// R16: ONE persistent kernel runs the whole post-gate graph:
//   P1: GEMM1 tiles (n-fastest per expert) + interleaved W2-split slices
//   P2: GEMM2 tiles, gated on per-(expert,mtile) done counters
//   P3: combine slices, gated on global GEMM2 counter
// Release/acquire via __threadfence + atomics; GEMM loads are cp.async.cg
// (L2-coherent). GEMM inner loop = R11 (128x128, 64x32 warp tile, 2 CTA/SM).
// Launches: split_x(0), prep = W1 split + gate (1), fused(2).
// ---------------------------------------------------------------------------

#define HID   1024
#define INTER 4096
#define NEXP  8
#define TMAX  8192
#define NSLOT (2 * TMAX)

#define WCNT ((size_t)NEXP * (size_t)INTER * (size_t)HID)
#define XOFF ((size_t)TMAX * (size_t)HID)
#define HOFF ((size_t)NSLOT * (size_t)INTER)

#define NSPLIT  1024                  // W2 slices (32768 elems each)
#define SLICE4  8192                  // float4 per W2 slice

__device__ __half d_xs[XOFF];
__device__ __half d_w1h[WCNT];
__device__ __half d_w2h[WCNT];
__device__ __half d_hs[HOFF];
__device__ float  d_y[(size_t)NSLOT * (size_t)HID];
__device__ float  d_slot_w[NSLOT];
__device__ int    d_slot_list[NEXP * TMAX];
__device__ int    d_counts[NEXP];
__device__ int    d_work;
__device__ int    d_done1[NEXP * 128];   // per-(e, mtile) GEMM1 n-tiles done
__device__ int    d_done_w2;
__device__ int    d_done2;

// ------------------------------ PTX helpers --------------------------------

__device__ __forceinline__ uint32_t smem_u32(const void* p) {
    uint32_t a;
    asm("{ .reg .u64 t; cvta.to.shared.u64 t, %1; cvt.u32.u64 %0, t; }"
        : "=r"(a) : "l"(p));
    return a;
}

__device__ __forceinline__ void cp16(uint32_t saddr, const void* g) {
    asm volatile("cp.async.cg.shared.global [%0], [%1], 16;"
                 :: "r"(saddr), "l"(g));
}
#define CP_COMMIT() asm volatile("cp.async.commit_group;" ::: "memory")
#define CP_WAIT(N)  asm volatile("cp.async.wait_group %0;" :: "n"(N) : "memory")

__device__ __forceinline__ void ldm_x4(uint32_t* r, uint32_t addr) {
    asm volatile("ldmatrix.sync.aligned.m8n8.x4.shared.b16 {%0,%1,%2,%3}, [%4];"
                 : "=r"(r[0]), "=r"(r[1]), "=r"(r[2]), "=r"(r[3]) : "r"(addr));
}

__device__ __forceinline__ void mma16816(float* c, const uint32_t* a,
                                         uint32_t b0, uint32_t b1) {
    asm volatile(
        "mma.sync.aligned.m16n8k16.row.col.f32.f16.f16.f32 "
        "{%0,%1,%2,%3}, {%4,%5,%6,%7}, {%8,%9}, {%0,%1,%2,%3};"
        : "+f"(c[0]), "+f"(c[1]), "+f"(c[2]), "+f"(c[3])
        : "r"(a[0]), "r"(a[1]), "r"(a[2]), "r"(a[3]), "r"(b0), "r"(b1));
}

__device__ __forceinline__ ushort4 cvt4h(float4 v) {
    return make_ushort4(__half_as_ushort(__float2half_rn(v.x)),
                        __half_as_ushort(__float2half_rn(v.y)),
                        __half_as_ushort(__float2half_rn(v.z)),
                        __half_as_ushort(__float2half_rn(v.w)));
}

// ---------------------------- split_x + state zero -------------------------

__global__ void split_x_kernel(const float* __restrict__ src, size_t n4) {
    if (blockIdx.x == 0) {
        if (threadIdx.x < NEXP) d_counts[threadIdx.x] = 0;
        if (threadIdx.x == 0) { d_work = 0; d_done_w2 = 0; d_done2 = 0; }
        for (int k = threadIdx.x; k < NEXP * 128; k += 256) d_done1[k] = 0;
    }
    size_t i = (size_t)blockIdx.x * blockDim.x + threadIdx.x;
    if (i >= n4) return;
    ((ushort4*)d_xs)[i] = cvt4h(((const float4*)src)[i]);
}

// ------------------- prep: W1 split + gate, one launch ---------------------

__global__ void prep_kernel(const float* __restrict__ W1, size_t nw4, int nsb,
                            const float* __restrict__ x,
                            const float* __restrict__ gw, int T) {
    if ((int)blockIdx.x < nsb) {
        size_t i = (size_t)blockIdx.x * blockDim.x + threadIdx.x;
        if (i < nw4)
            ((ushort4*)d_w1h)[i] = cvt4h(((const float4*)W1)[i]);
        return;
    }
    // gating (Kahan fp32)
    int warp = (((int)blockIdx.x - nsb) * (int)blockDim.x +
                (int)threadIdx.x) >> 5;
    int lane = threadIdx.x & 31;
    if (warp >= T) return;
    const float* xr = x + (size_t)warp * HID;

    float acc[NEXP], cmp[NEXP];
#pragma unroll
    for (int e = 0; e < NEXP; e++) { acc[e] = 0.0f; cmp[e] = 0.0f; }
#pragma unroll 4
    for (int i = lane; i < HID; i += 32) {
        float xv = xr[i];
#pragma unroll
        for (int e = 0; e < NEXP; e++) {
            float prod = xv * gw[e * HID + i];
            float y = prod - cmp[e];
            float t = acc[e] + y;
            cmp[e] = (t - acc[e]) - y;
            acc[e] = t;
        }
    }
#pragma unroll
    for (int e = 0; e < NEXP; e++) {
#pragma unroll
        for (int o = 16; o > 0; o >>= 1)
            acc[e] += __shfl_down_sync(0xffffffffu, acc[e], o);
    }
    if (lane == 0) {
        float bv = -1e30f, sv = -1e30f;
        int bi = 0, si = 0;
#pragma unroll
        for (int e = 0; e < NEXP; e++) {
            float val = acc[e];
            if (val > bv) { sv = bv; si = bi; bv = val; bi = e; }
            else if (val > sv) { sv = val; si = e; }
        }
        float e1 = expf(sv - bv);
        float s = 1.0f + e1;
        d_slot_w[2 * warp + 0] = 1.0f / s;
        d_slot_w[2 * warp + 1] = e1 / s;
        int p0 = atomicAdd(&d_counts[bi], 1);
        d_slot_list[bi * TMAX + p0] = 2 * warp;
        int p1 = atomicAdd(&d_counts[si], 1);
        d_slot_list[si * TMAX + p1] = 2 * warp + 1;
    }
}

// --------------------------- fused persistent ------------------------------

#define BM 128
#define BN 128
#define BK 64
#define NT1 (INTER / BN)              // 32
#define NT2 (HID / BN)                // 8

#define SM_BUF 1024
#define AREG   16384
#define BOFF   AREG
#define BUFSZ  (AREG + 16384)         // 32768
#define NBUF   3
#define SMEM_TOTAL (SM_BUF + NBUF * BUFSZ)   // 99328 B; x2 CTAs = 194 KB/SM

#define NPERSIST 296

__global__ void __launch_bounds__(256, 2)
moe_fused(const float* __restrict__ b1v, const float* __restrict__ b2v,
          const float* __restrict__ W2src, float* __restrict__ out, int T)
{
    extern __shared__ __align__(128) char smem[];
    const uint32_t sb = smem_u32(smem);
    const int tid = threadIdx.x;

    int* Srow   = (int*)smem;                 // [0, 512)
    int* s_tile = (int*)(smem + 512);

    int mt[NEXP];
    int total1 = 0, total2 = 0;
#pragma unroll
    for (int e = 0; e < NEXP; e++) {
        mt[e] = (d_counts[e] + BM - 1) / BM;
        total1 += mt[e] * NT1;
        total2 += mt[e] * NT2;
    }
    const int n1end = total1 + NSPLIT;        // total1 >= 4096 always
    const int n2end = n1end + total2;
    const int nc3   = T / 32;                 // combine slices
    const int total_ids = n2end + nc3;

    // ---- tile-independent constants --------------------------------------
    const int wid = tid >> 5, l = tid & 31;
    const int wm = wid >> 2;
    const int wn = wid & 3;
    const int g  = l >> 2, tg = l & 3;

    const int arow0 = wm * 64 + (l & 15);
    const uint32_t a_rowoff = (uint32_t)arow0 * 128u;
    const int axr = arow0 & 7;
    const int a_chsel = l >> 4;

    const int brow0 = wn * 32 + ((l >> 4) << 3) + (l & 7);
    const uint32_t b_rowoff = BOFF + (uint32_t)brow0 * 128u;
    const int bxr = brow0 & 7;
    const int b_chsel = (l >> 3) & 1;

    const int lrow = tid >> 1;
    const int ach0 = (tid & 1) * 4;
    const uint32_t row_dst = (uint32_t)lrow * 128u;
    const int rx = lrow & 7;

    while (true) {
        if (tid == 0) *s_tile = atomicAdd(&d_work, 1);
        __syncthreads();                  // also guards Srow reuse
        const int id = *s_tile;
        if (id >= total_ids) break;

        // =================== P3: combine slice ============================
        if (id >= n2end) {
            if (tid == 0) {
                while (atomicAdd(&d_done2, 0) < total2) {}
            }
            __syncthreads();
            const int sidx = id - n2end;
            const float4* y4 = (const float4*)d_y;
            float4* o4 = (float4*)out;
            int base = sidx * SLICE4 + tid;
#pragma unroll 8
            for (int k = 0; k < 32; k++) {
                int i = base + k * 256;
                int h4 = i & 255;
                int t  = i >> 8;
                float4 a = __ldcg(y4 + (size_t)(2 * t) * 256 + h4);
                float4 b = __ldcg(y4 + (size_t)(2 * t + 1) * 256 + h4);
                float4 r;
                r.x = a.x + b.x; r.y = a.y + b.y;
                r.z = a.z + b.z; r.w = a.w + b.w;
                o4[i] = r;
            }
            continue;
        }

        // =================== P1 id decode (+ W2 slice) ====================
        bool g1;
        int t;
        if (id < n1end) {
            g1 = true;
            if (id < 5 * NSPLIT) {
                if ((id % 5) == 4) {
                    // ---- W2 split slice ----
                    const int sidx = id / 5;
                    const float4* src =
                        (const float4*)W2src + (size_t)sidx * SLICE4 + tid;
                    ushort4* dst =
                        (ushort4*)d_w2h + (size_t)sidx * SLICE4 + tid;
#pragma unroll 8
                    for (int k = 0; k < 32; k++)
                        dst[k * 256] = cvt4h(src[k * 256]);
                    __threadfence();
                    __syncthreads();
                    if (tid == 0) atomicAdd(&d_done_w2, 1);
                    continue;
                }
                t = id - (id + 1) / 5;
            } else {
                t = id - NSPLIT;
            }
        } else {
            g1 = false;
            t = id - n1end;
        }

        const int kdim = g1 ? HID : INTER;
        const int nc   = kdim / BK;
        const int ndim = g1 ? INTER : HID;
        const int nt   = g1 ? NT1 : NT2;

        // map t -> (e, m, n); n fastest (groups complete in m order)
        int e = 0;
#pragma unroll
        for (int k = 0; k < NEXP - 1; k++) {
            int sz = mt[e] * nt;
            if (t >= sz) { t -= sz; e++; }
        }
        const int m  = t / nt;
        const int n  = t % nt;
        const int r0 = m * BM;
        const int n0 = n * BN;
        const int cnt = d_counts[e];

        // P2 dependency: W2 converted + h-group (e, m) complete
        if (!g1) {
            if (tid == 0) {
                while (atomicAdd(&d_done_w2, 0) < NSPLIT) {}
                while (atomicAdd(&d_done1[e * 128 + m], 0) < NT1) {}
            }
            __syncthreads();
        }

        if (tid < BM) {
            int idx = r0 + tid;
            Srow[tid] = (idx < cnt) ? d_slot_list[e * TMAX + idx] : -1;
        }
        __syncthreads();

        int s_ld = Srow[lrow];
        const __half* aptr;
        if (g1) {
            int tok = (s_ld < 0) ? 0 : (s_ld >> 1);
            aptr = d_xs + (size_t)tok * HID;
        } else {
            aptr = d_hs + (size_t)(s_ld < 0 ? 0 : s_ld) * INTER;
        }
        const __half* wbase = g1 ? d_w1h : d_w2h;
        const __half* bptr = wbase + ((size_t)e * ndim + n0 + lrow) * kdim;

        auto load_chunk = [&](int c) {
            const uint32_t dbuf = sb + SM_BUF + (uint32_t)(c % NBUF) * BUFSZ;
            const int koff = c * BK;
#pragma unroll
            for (int i = 0; i < 4; i++) {
                int ch = ach0 + i;
                uint32_t sw = (uint32_t)((ch ^ rx) << 4);
                cp16(dbuf + row_dst + sw, aptr + koff + ch * 8);
                cp16(dbuf + BOFF + row_dst + sw, bptr + koff + ch * 8);
            }
            CP_COMMIT();
        };

        float acc[4][4][4];
#pragma unroll
        for (int a = 0; a < 4; a++)
#pragma unroll
            for (int b = 0; b < 4; b++)
#pragma unroll
                for (int q = 0; q < 4; q++) acc[a][b][q] = 0.0f;

        load_chunk(0);
        load_chunk(1);

        for (int c = 0; c < nc; c++) {
            if (c + 1 < nc) { CP_WAIT(1); }
            else            { CP_WAIT(0); }
            __syncthreads();
            if (c + 2 < nc) load_chunk(c + 2);

            const uint32_t sbuf = sb + SM_BUF + (uint32_t)(c % NBUF) * BUFSZ;
#pragma unroll
            for (int ks = 0; ks < BK / 16; ks++) {
                uint32_t ah[4][4];
                const uint32_t aoff =
                    (uint32_t)(((2 * ks + a_chsel) ^ axr) << 4);
#pragma unroll
                for (int mi = 0; mi < 4; mi++) {
                    uint32_t addr = sbuf + a_rowoff +
                                    (uint32_t)mi * 2048u + aoff;
                    ldm_x4(ah[mi], addr);
                }
                const uint32_t boff =
                    (uint32_t)(((2 * ks + b_chsel) ^ bxr) << 4);
#pragma unroll
                for (int jp = 0; jp < 2; jp++) {
                    uint32_t baddr = sbuf + b_rowoff +
                                     (uint32_t)jp * 2048u + boff;
                    uint32_t bh[4];
                    ldm_x4(bh, baddr);
#pragma unroll
                    for (int mi = 0; mi < 4; mi++) {
                        mma16816(acc[mi][2 * jp],     ah[mi], bh[0], bh[1]);
                        mma16816(acc[mi][2 * jp + 1], ah[mi], bh[2], bh[3]);
                    }
                }
            }
        }

        // ---- epilogue -----------------------------------------------------
        const float* bias = (g1 ? b1v : b2v) + (size_t)e * ndim;
#pragma unroll
        for (int mi = 0; mi < 4; mi++) {
            const int lr0 = wm * 64 + mi * 16 + g;
            const int slotA = Srow[lr0];
            const int slotB = Srow[lr0 + 8];
#pragma unroll
            for (int nj = 0; nj < 4; nj++) {
                const int col = n0 + wn * 32 + nj * 8 + 2 * tg;
                const float b0 = bias[col], b1 = bias[col + 1];
                if (g1) {
                    if (slotA >= 0) {
                        float v0 = acc[mi][nj][0] + b0;
                        float v1 = acc[mi][nj][1] + b1;
                        v0 = 0.5f * v0 *
                             (1.0f + erff(v0 * 0.7071067811865475f));
                        v1 = 0.5f * v1 *
                             (1.0f + erff(v1 * 0.7071067811865475f));
                        *(__half2*)(d_hs + (size_t)slotA * INTER + col) =
                            __floats2half2_rn(v0, v1);
                    }
                    if (slotB >= 0) {
                        float v0 = acc[mi][nj][2] + b0;
                        float v1 = acc[mi][nj][3] + b1;
                        v0 = 0.5f * v0 *
                             (1.0f + erff(v0 * 0.7071067811865475f));
                        v1 = 0.5f * v1 *
                             (1.0f + erff(v1 * 0.7071067811865475f));
                        *(__half2*)(d_hs + (size_t)slotB * INTER + col) =
                            __floats2half2_rn(v0, v1);
                    }
                } else {
                    if (slotA >= 0) {
                        float wmul = d_slot_w[slotA];
                        float2 o;
                        o.x = (acc[mi][nj][0] + b0) * wmul;
                        o.y = (acc[mi][nj][1] + b1) * wmul;
                        *(float2*)(d_y + (size_t)slotA * HID + col) = o;
                    }
                    if (slotB >= 0) {
                        float wmul = d_slot_w[slotB];
                        float2 o;
                        o.x = (acc[mi][nj][2] + b0) * wmul;
                        o.y = (acc[mi][nj][3] + b1) * wmul;
                        *(float2*)(d_y + (size_t)slotB * HID + col) = o;
                    }
                }
            }
        }

        // release: make this tile's stores visible, then count it
        __threadfence();
        __syncthreads();
        if (tid == 0) {
            if (g1) atomicAdd(&d_done1[e * 128 + m], 1);
            else    atomicAdd(&d_done2, 1);
        }
    }
}

// ------------------------------- launch ------------------------------------

extern "C" void kernel_launch(void* const* d_in, const int* in_sizes, int n_in,
                              void* d_out, int out_size) {
    const float* x  = (const float*)d_in[0];
    const float* gw = (const float*)d_in[1];
    const float* W1 = (const float*)d_in[2];
    const float* b1 = (const float*)d_in[3];
    const float* W2 = (const float*)d_in[4];
    const float* b2 = (const float*)d_in[5];
    float* out = (float*)d_out;

    int T = in_sizes[0] / HID;

    cudaFuncSetAttribute(moe_fused,
                         cudaFuncAttributeMaxDynamicSharedMemorySize,
                         SMEM_TOTAL);

    size_t nx4 = (size_t)T * HID / 4;
    size_t nw4 = WCNT / 4;
    int nsb = (int)((nw4 + 255) / 256);
    int ngb = (T + 7) / 8;

    // launch 0: x -> fp16 + zero all device state
    split_x_kernel<<<(unsigned)((nx4 + 255) / 256), 256>>>(x, nx4);
    // launch 1: W1 split + gate (independent work, one launch)
    prep_kernel<<<(unsigned)(nsb + ngb), 256>>>(W1, nw4, nsb, x, gw, T);
    // launch 2: fused persistent GEMM1 + W2split + GEMM2 + combine
    moe_fused<<<NPERSIST, 256, SMEM_TOTAL>>>(b1, b2, W2, out, T);
}